// round 9
// baseline (speedup 1.0000x reference)
#include <cuda_runtime.h>
#include <cuda_fp16.h>
#include <cstdint>

#define Tn 8192
#define Hn 1024
#define In 2816
#define En 8
#define MAXP 17408  // 16384 pairs + per-expert 128-alignment padding

// ------------------- device scratch (no allocations allowed) -----------------
__device__ int    g_cnt[En];
__device__ int    g_cur[En];
__device__ int    g_off[En + 1];
__device__ int    g_eid[Tn * 2];
__device__ float  g_ew[Tn * 2];
__device__ int    g_tok[MAXP];
__device__ float  g_wt[MAXP];
__device__ int    g_slots[Tn * 2];
__device__ __half g_xh[(size_t)MAXP * Hn];    // gathered x rows, fp16
__device__ __half g_hbh[(size_t)MAXP * In];   // silu(gate)*up, fp16
__device__ __half g_poh[(size_t)MAXP * Hn];   // per-pair weighted output, fp16

// ------------------- helpers -------------------------------------------------
__device__ __forceinline__ uint32_t smem_u32(const void* p) {
    uint32_t a;
    asm("{ .reg .u64 t; cvta.to.shared.u64 t, %1; cvt.u32.u64 %0, t; }" : "=r"(a) : "l"(p));
    return a;
}
__device__ __forceinline__ void cp16(uint32_t saddr, const void* gsrc) {
    asm volatile("cp.async.cg.shared.global [%0], [%1], 16;\n" :: "r"(saddr), "l"(gsrc));
}
// fp16 m16n8k16 mma, fp32 accumulate
__device__ __forceinline__ void mma16(float* c, const uint32_t* a, const uint32_t* b) {
    asm volatile(
        "mma.sync.aligned.m16n8k16.row.col.f32.f16.f16.f32 "
        "{%0,%1,%2,%3}, {%4,%5,%6,%7}, {%8,%9}, {%0,%1,%2,%3};\n"
        : "+f"(c[0]), "+f"(c[1]), "+f"(c[2]), "+f"(c[3])
        : "r"(a[0]), "r"(a[1]), "r"(a[2]), "r"(a[3]), "r"(b[0]), "r"(b[1]));
}
__device__ __forceinline__ void ldm4(uint32_t* r, uint32_t addr) {
    asm volatile("ldmatrix.sync.aligned.m8n8.x4.shared.b16 {%0,%1,%2,%3}, [%4];"
                 : "=r"(r[0]), "=r"(r[1]), "=r"(r[2]), "=r"(r[3]) : "r"(addr));
}
__device__ __forceinline__ uint32_t h2u(__half2 h) { return *(uint32_t*)&h; }

// smem per stage (halves): A 128x72 = 9216, B 256x72 = 18432 -> 27648 (55296 B)
static constexpr int STG_B = 55296;           // bytes per stage
static constexpr int BOFF_B = 9216 * 2;       // B offset within stage (bytes)
static constexpr int SMEM_BYTES = STG_B * 3;  // 165,888 B (3 stages)

static constexpr int NTHREADS = 320;  // 256 compute + 64 loader

// ------------------- kernel: reset per-call state -----------------------------
__global__ void k_init() {
    int i = blockIdx.x * blockDim.x + threadIdx.x;
    if (i < En) { g_cnt[i] = 0; g_cur[i] = 0; }
    for (int s = i; s < MAXP; s += gridDim.x * blockDim.x) {
        g_tok[s] = -1;
        g_wt[s] = 0.0f;
    }
}

// ------------------- kernel: router ------------------------------------------
__global__ void k_router(const float* __restrict__ logits) {
    int t = blockIdx.x * blockDim.x + threadIdx.x;
    if (t >= Tn) return;
    float v[En];
#pragma unroll
    for (int e = 0; e < En; e++) v[e] = logits[t * En + e];
    int b0 = 0; float m0 = v[0];
#pragma unroll
    for (int e = 1; e < En; e++) if (v[e] > m0) { m0 = v[e]; b0 = e; }
    int b1 = -1; float m1 = -3.0e38f;
#pragma unroll
    for (int e = 0; e < En; e++) if (e != b0 && v[e] > m1) { m1 = v[e]; b1 = e; }
    float e1 = expf(m1 - m0);
    float inv = 1.0f / (1.0f + e1);
    g_eid[2 * t] = b0;     g_ew[2 * t] = inv;
    g_eid[2 * t + 1] = b1; g_ew[2 * t + 1] = e1 * inv;
    atomicAdd(&g_cnt[b0], 1);
    atomicAdd(&g_cnt[b1], 1);
}

// ------------------- kernel: 128-aligned offsets ------------------------------
__global__ void k_off() {
    if (threadIdx.x == 0 && blockIdx.x == 0) {
        int o = 0;
        g_off[0] = 0;
        for (int e = 0; e < En; e++) {
            o += (g_cnt[e] + 127) & ~127;
            g_off[e + 1] = o;
        }
    }
}

// ------------------- kernel: scatter ------------------------------------------
__global__ void k_scatter() {
    int t = blockIdx.x * blockDim.x + threadIdx.x;
    if (t >= Tn) return;
#pragma unroll
    for (int k = 0; k < 2; k++) {
        int e = g_eid[2 * t + k];
        int pos = atomicAdd(&g_cur[e], 1);
        int s = g_off[e] + pos;
        g_tok[s] = t;
        g_wt[s] = g_ew[2 * t + k];
        g_slots[2 * t + k] = s;
    }
}

// ------------------- kernel: gather x rows -> fp16 ----------------------------
__global__ void k_gather(const float* __restrict__ x) {
    int s = blockIdx.x;
    int tok = g_tok[s];
    uint2 pk = { 0u, 0u };
    if (tok >= 0) {
        float4 v = *(const float4*)&x[(size_t)tok * Hn + threadIdx.x * 4];
        pk.x = h2u(__floats2half2_rn(v.x, v.y));
        pk.y = h2u(__floats2half2_rn(v.z, v.w));
    }
    *(uint2*)&g_xh[(size_t)s * Hn + threadIdx.x * 4] = pk;
}

// =============================================================================
// GEMM mainloop: 256 compute threads (ldmatrix + m16n8k16, identical to proven
// R7 path) + 64 loader threads that cp.async the fp16 A tile and LDG+CVT+STS
// the fp32 weight B tile. 3 stages, lookahead 2, one barrier per chunk.
// =============================================================================

__device__ __forceinline__ int ldm_lane_off(int lane) {
    int lr = lane & 7, grp = lane >> 3;
    int rowoff = lr + (grp & 1) * 8;
    int coloff = (grp >> 1) * 8;
    return (rowoff * 72 + coloff) * 2;
}

// loader: convert+store one B row chunk (64 fp32 -> 64 fp16, 128 B)
__device__ __forceinline__ void load_b_row(const float* wrow, int chunk, uint32_t sdst) {
    const float4* s4 = (const float4*)(wrow + chunk * 64);
    float4 t[16];
#pragma unroll
    for (int i = 0; i < 16; i++) t[i] = s4[i];
#pragma unroll
    for (int i = 0; i < 8; i++) {
        uint4 v;
        v.x = h2u(__floats2half2_rn(t[2 * i].x, t[2 * i].y));
        v.y = h2u(__floats2half2_rn(t[2 * i].z, t[2 * i].w));
        v.z = h2u(__floats2half2_rn(t[2 * i + 1].x, t[2 * i + 1].y));
        v.w = h2u(__floats2half2_rn(t[2 * i + 1].z, t[2 * i + 1].w));
        asm volatile("st.shared.v4.b32 [%0], {%1,%2,%3,%4};"
                     :: "r"(sdst), "r"(v.x), "r"(v.y), "r"(v.z), "r"(v.w) : "memory");
        sdst += 16;
    }
}

#define LOADER_CHUNK(c, st) do {                                                   \
    _Pragma("unroll")                                                              \
    for (int q = 0; q < 16; q++) cp16(aOff[q] + (st) * STG_B, aSrc[q] + (c) * 64); \
    asm volatile("cp.async.commit_group;" ::: "memory");                           \
    _Pragma("unroll")                                                              \
    for (int rr = 0; rr < 4; rr++)                                                 \
        load_b_row(wrow[rr], (c), srow[rr] + (st) * STG_B);                        \
} while (0)

#define GEMM_MAINLOOP(NC)                                                          \
    if (tid >= 256) {                                                              \
        LOADER_CHUNK(0, 0);                                                        \
        LOADER_CHUNK(1, 1);                                                        \
        asm volatile("cp.async.wait_group 1;" ::: "memory");                       \
    }                                                                              \
    __syncthreads();                                                               \
    for (int i = 0; i < (NC); i++) {                                               \
        const int st = i % 3;                                                      \
        if (tid < 256) {                                                           \
            const uint32_t aS = sb + st * STG_B;                                   \
            const uint32_t bS = sb + BOFF_B + st * STG_B;                          \
            _Pragma("unroll")                                                      \
            for (int ks = 0; ks < 4; ks++) {                                       \
                const int k0b = ks * 32;                                           \
                uint32_t af[4][4], bf[8][2];                                       \
                _Pragma("unroll")                                                  \
                for (int mi = 0; mi < 4; mi++)                                     \
                    ldm4(af[mi], aS + (mBase + mi * 16) * 144 + k0b + loff);       \
                _Pragma("unroll")                                                  \
                for (int nj = 0; nj < 4; nj++) {                                   \
                    uint32_t t4[4];                                                \
                    ldm4(t4, bS + (nBase + nj * 16) * 144 + k0b + loff);           \
                    bf[nj * 2][0] = t4[0]; bf[nj * 2 + 1][0] = t4[1];              \
                    bf[nj * 2][1] = t4[2]; bf[nj * 2 + 1][1] = t4[3];              \
                }                                                                  \
                _Pragma("unroll")                                                  \
                for (int mi = 0; mi < 4; mi++)                                     \
                    _Pragma("unroll")                                              \
                    for (int ni = 0; ni < 8; ni++) mma16(acc[mi][ni], af[mi], bf[ni]); \
            }                                                                      \
        } else {                                                                   \
            if (i + 2 < (NC)) {                                                    \
                LOADER_CHUNK(i + 2, (i + 2) % 3);                                  \
                asm volatile("cp.async.wait_group 1;" ::: "memory");               \
            } else {                                                               \
                asm volatile("cp.async.wait_group 0;" ::: "memory");               \
            }                                                                      \
        }                                                                          \
        __syncthreads();                                                           \
    }

// =============================================================================
// GEMM1: h = silu(x W1^T) * (x W3^T). B-rows 0..127 = gate, 128..255 = up.
// =============================================================================
__global__ __launch_bounds__(NTHREADS, 1) void k_gemm1(const float* __restrict__ w13) {
    extern __shared__ __align__(16) char smraw[];
    const int mtile = blockIdx.x, ntile = blockIdx.y;  // mtile fast (A L2-reuse)
    if (mtile * 128 >= g_off[En]) return;
    int e = 0;
#pragma unroll
    for (int i = 0; i < En; i++) if (mtile * 128 >= g_off[i + 1]) e = i + 1;
    const int n0 = ntile * 128;
    const int tid = threadIdx.x;
    const uint32_t sb = smem_u32(smraw);

    // ---- loader state (tid >= 256) ----
    const __half* aSrc[16]; uint32_t aOff[16];
    const float* wrow[4];   uint32_t srow[4];
    if (tid >= 256) {
        int lt = tid - 256;  // 0..63
#pragma unroll
        for (int q = 0; q < 16; q++) {
            int u = lt + q * 64, r = u >> 3, sg = u & 7;
            aSrc[q] = g_xh + (size_t)(mtile * 128 + r) * Hn + sg * 8;
            aOff[q] = sb + (r * 72 + sg * 8) * 2;
        }
#pragma unroll
        for (int rr = 0; rr < 4; rr++) {
            int R = lt + rr * 64;
            wrow[rr] = (R < 128)
                ? (w13 + ((size_t)e * 2 * In + n0 + R) * Hn)
                : (w13 + ((size_t)e * 2 * In + In + n0 + (R - 128)) * Hn);
            srow[rr] = sb + BOFF_B + R * 144;
        }
    }

    // ---- compute state (tid < 256) ----
    const int w = tid >> 5, lane = tid & 31;
    const int mBase = (w & 1) * 64, nBase = (w >> 1) * 64;
    const int qr = lane >> 2, qc = lane & 3;
    const int loff = ldm_lane_off(lane);

    float acc[4][8][4];
#pragma unroll
    for (int a = 0; a < 4; a++)
#pragma unroll
        for (int b = 0; b < 8; b++)
#pragma unroll
            for (int c = 0; c < 4; c++) acc[a][b][c] = 0.0f;

    GEMM_MAINLOOP(Hn / 64)

    // ---- epilogue: gate warps stage to smem; up warps compute silu(g)*u ------
    float* sE = (float*)smraw;  // 128 x pitch-130 floats = 66,560 B (fits)
    if (tid < 256 && nBase < 128) {
#pragma unroll
        for (int mi = 0; mi < 4; mi++)
#pragma unroll
            for (int ni = 0; ni < 8; ni++) {
                int r = mBase + mi * 16 + qr;
                int c = nBase + ni * 8 + qc * 2;
                sE[r * 130 + c] = acc[mi][ni][0];
                sE[r * 130 + c + 1] = acc[mi][ni][1];
                sE[(r + 8) * 130 + c] = acc[mi][ni][2];
                sE[(r + 8) * 130 + c + 1] = acc[mi][ni][3];
            }
    }
    __syncthreads();
    if (tid < 256 && nBase >= 128) {
        const size_t rowBase = (size_t)mtile * 128;
#pragma unroll
        for (int mi = 0; mi < 4; mi++)
#pragma unroll
            for (int ni = 0; ni < 8; ni++) {
                int j = (nBase - 128) + ni * 8 + qc * 2;
#pragma unroll
                for (int half = 0; half < 2; half++) {
                    int r = mBase + mi * 16 + qr + half * 8;
                    float g0 = sE[r * 130 + j];
                    float g1 = sE[r * 130 + j + 1];
                    float u0 = acc[mi][ni][half * 2];
                    float u1 = acc[mi][ni][half * 2 + 1];
                    float h0 = g0 * (1.0f / (1.0f + __expf(-g0))) * u0;
                    float h1 = g1 * (1.0f / (1.0f + __expf(-g1))) * u1;
                    __half2 hv = __floats2half2_rn(h0, h1);
                    *(__half2*)&g_hbh[(rowBase + r) * In + (size_t)n0 + j] = hv;
                }
            }
    }
}

// =============================================================================
// GEMM2: po = wt * (h W2^T).  CTA tile M=128 x N=256 out cols, K = In.
// =============================================================================
__global__ __launch_bounds__(NTHREADS, 1) void k_gemm2(const float* __restrict__ w2) {
    extern __shared__ __align__(16) char smraw[];
    const int ntile = blockIdx.x, mtile = blockIdx.y;  // ntile fast (w2 L2-resident)
    if (mtile * 128 >= g_off[En]) return;
    int e = 0;
#pragma unroll
    for (int i = 0; i < En; i++) if (mtile * 128 >= g_off[i + 1]) e = i + 1;
    const int n0 = ntile * 256;
    const int tid = threadIdx.x;
    const uint32_t sb = smem_u32(smraw);

    const __half* aSrc[16]; uint32_t aOff[16];
    const float* wrow[4];   uint32_t srow[4];
    if (tid >= 256) {
        int lt = tid - 256;
#pragma unroll
        for (int q = 0; q < 16; q++) {
            int u = lt + q * 64, r = u >> 3, sg = u & 7;
            aSrc[q] = g_hbh + (size_t)(mtile * 128 + r) * In + sg * 8;
            aOff[q] = sb + (r * 72 + sg * 8) * 2;
        }
#pragma unroll
        for (int rr = 0; rr < 4; rr++) {
            int R = lt + rr * 64;
            wrow[rr] = w2 + ((size_t)e * Hn + n0 + R) * In;
            srow[rr] = sb + BOFF_B + R * 144;
        }
    }

    const int w = tid >> 5, lane = tid & 31;
    const int mBase = (w & 1) * 64, nBase = (w >> 1) * 64;
    const int qr = lane >> 2, qc = lane & 3;
    const int loff = ldm_lane_off(lane);

    float acc[4][8][4];
#pragma unroll
    for (int a = 0; a < 4; a++)
#pragma unroll
        for (int b = 0; b < 8; b++)
#pragma unroll
            for (int c = 0; c < 4; c++) acc[a][b][c] = 0.0f;

    GEMM_MAINLOOP(In / 64)

    // ---- epilogue: scale by router weight, write per-pair fp16 output --------
    if (tid < 256) {
        const size_t rowBase = (size_t)mtile * 128;
#pragma unroll
        for (int mi = 0; mi < 4; mi++) {
#pragma unroll
            for (int half = 0; half < 2; half++) {
                int r = mBase + mi * 16 + qr + half * 8;
                float wt = g_wt[rowBase + r];
#pragma unroll
                for (int ni = 0; ni < 8; ni++) {
                    int c = nBase + ni * 8 + qc * 2;
                    __half2 hv = __floats2half2_rn(wt * acc[mi][ni][half * 2],
                                                   wt * acc[mi][ni][half * 2 + 1]);
                    *(__half2*)&g_poh[(rowBase + r) * Hn + (size_t)n0 + c] = hv;
                }
            }
        }
    }
}

// ------------------- combine: out[t] = po[slot0] + po[slot1] ------------------
__global__ void k_combine(float* __restrict__ out) {
    int t = blockIdx.x;
    int i = threadIdx.x;  // 256 threads x 4 halves
    int s0 = g_slots[2 * t], s1 = g_slots[2 * t + 1];
    uint2 pa = *(const uint2*)&g_poh[(size_t)s0 * Hn + i * 4];
    uint2 pb = *(const uint2*)&g_poh[(size_t)s1 * Hn + i * 4];
    float2 a0 = __half22float2(*(__half2*)&pa.x), a1 = __half22float2(*(__half2*)&pa.y);
    float2 b0 = __half22float2(*(__half2*)&pb.x), b1 = __half22float2(*(__half2*)&pb.y);
    float4 o;
    o.x = a0.x + b0.x; o.y = a0.y + b0.y; o.z = a1.x + b1.x; o.w = a1.y + b1.y;
    *(float4*)&out[(size_t)t * Hn + i * 4] = o;
}

// ------------------- launcher -------------------------------------------------
extern "C" void kernel_launch(void* const* d_in, const int* in_sizes, int n_in,
                              void* d_out, int out_size) {
    const float* x      = (const float*)d_in[0];
    const float* logits = (const float*)d_in[1];
    const float* w13    = (const float*)d_in[2];
    const float* w2     = (const float*)d_in[3];
    float* out = (float*)d_out;

    cudaFuncSetAttribute(k_gemm1, cudaFuncAttributeMaxDynamicSharedMemorySize, SMEM_BYTES);
    cudaFuncSetAttribute(k_gemm2, cudaFuncAttributeMaxDynamicSharedMemorySize, SMEM_BYTES);

    k_init<<<68, 256>>>();
    k_router<<<Tn / 256, 256>>>(logits);
    k_off<<<1, 32>>>();
    k_scatter<<<Tn / 256, 256>>>();
    k_gather<<<MAXP, 256>>>(x);
    k_gemm1<<<dim3(MAXP / 128, In / 128), NTHREADS, SMEM_BYTES>>>(w13);  // (136, 22)
    k_gemm2<<<dim3(Hn / 256, MAXP / 128), NTHREADS, SMEM_BYTES>>>(w2);   // (4, 136)
    k_combine<<<Tn, 256>>>(out);
}

// round 10
// speedup vs baseline: 2.8999x; 2.8999x over previous
#include <cuda_runtime.h>
#include <cuda_fp16.h>
#include <cstdint>

#define Tn 8192
#define Hn 1024
#define In 2816
#define En 8
#define MAXP 17408  // 16384 pairs + per-expert 128-alignment padding

// ------------------- device scratch (no allocations allowed) -----------------
__device__ int    g_cnt[En];
__device__ int    g_cur[En];
__device__ int    g_off[En + 1];
__device__ int    g_eid[Tn * 2];
__device__ float  g_ew[Tn * 2];
__device__ int    g_tok[MAXP];
__device__ float  g_wt[MAXP];
__device__ int    g_slots[Tn * 2];
__device__ __half g_xh[(size_t)MAXP * Hn];           // gathered x rows, fp16
__device__ __half g_hbh[(size_t)MAXP * In];          // silu(gate)*up, fp16
__device__ __half g_poh[(size_t)MAXP * Hn];          // per-pair weighted out, fp16
__device__ __half g_w13h[(size_t)En * 2 * In * Hn];  // fp16 w13 (92MB)
__device__ __half g_w2h[(size_t)En * Hn * In];       // fp16 w2  (46MB)

// ------------------- helpers -------------------------------------------------
__device__ __forceinline__ uint32_t smem_u32(const void* p) {
    uint32_t a;
    asm("{ .reg .u64 t; cvta.to.shared.u64 t, %1; cvt.u32.u64 %0, t; }" : "=r"(a) : "l"(p));
    return a;
}
__device__ __forceinline__ void cp16(uint32_t saddr, const void* gsrc) {
    asm volatile("cp.async.cg.shared.global [%0], [%1], 16;\n" :: "r"(saddr), "l"(gsrc));
}
// fp16 m16n8k16 mma, fp32 accumulate
__device__ __forceinline__ void mma16(float* c, const uint32_t* a, const uint32_t* b) {
    asm volatile(
        "mma.sync.aligned.m16n8k16.row.col.f32.f16.f16.f32 "
        "{%0,%1,%2,%3}, {%4,%5,%6,%7}, {%8,%9}, {%0,%1,%2,%3};\n"
        : "+f"(c[0]), "+f"(c[1]), "+f"(c[2]), "+f"(c[3])
        : "r"(a[0]), "r"(a[1]), "r"(a[2]), "r"(a[3]), "r"(b[0]), "r"(b[1]));
}
__device__ __forceinline__ void ldm4(uint32_t* r, uint32_t addr) {
    asm volatile("ldmatrix.sync.aligned.m8n8.x4.shared.b16 {%0,%1,%2,%3}, [%4];"
                 : "=r"(r[0]), "=r"(r[1]), "=r"(r[2]), "=r"(r[3]) : "r"(addr));
}
__device__ __forceinline__ uint32_t h2u(__half2 h) { return *(uint32_t*)&h; }

// smem per stage (halves): A 128x72 = 9216, B 256x72 = 18432 -> 27648 (55296 B)
static constexpr int STG_B = 55296;           // bytes per stage
static constexpr int BOFF_B = 9216 * 2;       // B offset within stage (bytes)
static constexpr int SMEM_BYTES = STG_B * 3;  // 165,888 B (3 stages)

// ------------------- kernel: convert weights to fp16 (+ state init) ----------
__global__ void k_cvtw(const float* __restrict__ w13, const float* __restrict__ w2) {
    long gid = (long)blockIdx.x * blockDim.x + threadIdx.x;
    if (gid < En) { g_cnt[gid] = 0; g_cur[gid] = 0; }
    const long stride = (long)gridDim.x * blockDim.x;
    for (long s = gid; s < MAXP; s += stride) {
        g_tok[s] = -1;
        g_wt[s] = 0.0f;
    }
    const long N1 = (long)En * 2 * In * Hn / 4;
    const long N2 = (long)En * Hn * In / 4;
    for (long i = gid; i < N1 + N2; i += stride) {
        float4 v = (i < N1) ? ((const float4*)w13)[i] : ((const float4*)w2)[i - N1];
        uint2 pk;
        pk.x = h2u(__floats2half2_rn(v.x, v.y));
        pk.y = h2u(__floats2half2_rn(v.z, v.w));
        if (i < N1) ((uint2*)g_w13h)[i] = pk;
        else        ((uint2*)g_w2h)[i - N1] = pk;
    }
}

// ------------------- kernel: router ------------------------------------------
__global__ void k_router(const float* __restrict__ logits) {
    int t = blockIdx.x * blockDim.x + threadIdx.x;
    if (t >= Tn) return;
    float v[En];
#pragma unroll
    for (int e = 0; e < En; e++) v[e] = logits[t * En + e];
    int b0 = 0; float m0 = v[0];
#pragma unroll
    for (int e = 1; e < En; e++) if (v[e] > m0) { m0 = v[e]; b0 = e; }
    int b1 = -1; float m1 = -3.0e38f;
#pragma unroll
    for (int e = 0; e < En; e++) if (e != b0 && v[e] > m1) { m1 = v[e]; b1 = e; }
    float e1 = expf(m1 - m0);
    float inv = 1.0f / (1.0f + e1);
    g_eid[2 * t] = b0;     g_ew[2 * t] = inv;
    g_eid[2 * t + 1] = b1; g_ew[2 * t + 1] = e1 * inv;
    atomicAdd(&g_cnt[b0], 1);
    atomicAdd(&g_cnt[b1], 1);
}

// ------------------- kernel: 128-aligned offsets ------------------------------
__global__ void k_off() {
    if (threadIdx.x == 0 && blockIdx.x == 0) {
        int o = 0;
        g_off[0] = 0;
        for (int e = 0; e < En; e++) {
            o += (g_cnt[e] + 127) & ~127;
            g_off[e + 1] = o;
        }
    }
}

// ------------------- kernel: scatter ------------------------------------------
__global__ void k_scatter() {
    int t = blockIdx.x * blockDim.x + threadIdx.x;
    if (t >= Tn) return;
#pragma unroll
    for (int k = 0; k < 2; k++) {
        int e = g_eid[2 * t + k];
        int pos = atomicAdd(&g_cur[e], 1);
        int s = g_off[e] + pos;
        g_tok[s] = t;
        g_wt[s] = g_ew[2 * t + k];
        g_slots[2 * t + k] = s;
    }
}

// ------------------- kernel: gather x rows -> fp16 ----------------------------
__global__ void k_gather(const float* __restrict__ x) {
    int s = blockIdx.x;
    int tok = g_tok[s];
    uint2 pk = { 0u, 0u };
    if (tok >= 0) {
        float4 v = *(const float4*)&x[(size_t)tok * Hn + threadIdx.x * 4];
        pk.x = h2u(__floats2half2_rn(v.x, v.y));
        pk.y = h2u(__floats2half2_rn(v.z, v.w));
    }
    *(uint2*)&g_xh[(size_t)s * Hn + threadIdx.x * 4] = pk;
}

// =============================================================================
// Shared GEMM mainloop (proven R7 path).
// CTA tile M=128 x 256 B-rows, fp16 m16n8k16, K-chunk = 64 halves (128 B/row),
// pitch-72 smem rows, 3-stage cp.async pipeline, ldmatrix fragment loads.
// 8 warps of 64x64 (warp m = (w&1)*64, n = (w>>1)*64).
// =============================================================================

__device__ __forceinline__ int ldm_lane_off(int lane) {
    int lr = lane & 7, grp = lane >> 3;
    int rowoff = lr + (grp & 1) * 8;
    int coloff = (grp >> 1) * 8;
    return (rowoff * 72 + coloff) * 2;
}

#define GEMM_MAINLOOP(NC)                                                          \
    /* prologue: fill stages 0,1,2 */                                              \
    _Pragma("unroll")                                                              \
    for (int c = 0; c < 3; c++) {                                                  \
        _Pragma("unroll")                                                          \
        for (int q = 0; q < 4; q++) cp16(sAo[q] + c * STG_B, pA[q] + c * 64);      \
        _Pragma("unroll")                                                          \
        for (int q = 0; q < 8; q++) cp16(sBo[q] + c * STG_B, pB[q] + c * 64);      \
        asm volatile("cp.async.commit_group;" ::: "memory");                       \
    }                                                                              \
    int st = 0;                                                                    \
    for (int i = 0; i < (NC); i++) {                                               \
        asm volatile("cp.async.wait_group 2;" ::: "memory");                       \
        __syncthreads();                                                           \
        const uint32_t aS = sbA + st * STG_B;                                      \
        const uint32_t bS = sbB + st * STG_B;                                      \
        _Pragma("unroll")                                                          \
        for (int ks = 0; ks < 4; ks++) {                                           \
            const int k0b = ks * 16 * 2;                                           \
            uint32_t af[4][4], bf[8][2];                                           \
            _Pragma("unroll")                                                      \
            for (int mi = 0; mi < 4; mi++)                                         \
                ldm4(af[mi], aS + (mBase + mi * 16) * 144 + k0b + loff);           \
            _Pragma("unroll")                                                      \
            for (int nj = 0; nj < 4; nj++) {                                       \
                uint32_t t4[4];                                                    \
                ldm4(t4, bS + (nBase + nj * 16) * 144 + k0b + loff);               \
                bf[nj * 2][0] = t4[0]; bf[nj * 2 + 1][0] = t4[1];                  \
                bf[nj * 2][1] = t4[2]; bf[nj * 2 + 1][1] = t4[3];                  \
            }                                                                      \
            _Pragma("unroll")                                                      \
            for (int mi = 0; mi < 4; mi++)                                         \
                _Pragma("unroll")                                                  \
                for (int ni = 0; ni < 8; ni++) mma16(acc[mi][ni], af[mi], bf[ni]); \
        }                                                                          \
        __syncthreads();                                                           \
        if (i + 3 < (NC)) {                                                        \
            _Pragma("unroll")                                                      \
            for (int q = 0; q < 4; q++) cp16(sAo[q] + st * STG_B, pA[q] + (i + 3) * 64); \
            _Pragma("unroll")                                                      \
            for (int q = 0; q < 8; q++) cp16(sBo[q] + st * STG_B, pB[q] + (i + 3) * 64); \
        }                                                                          \
        asm volatile("cp.async.commit_group;" ::: "memory");                       \
        if (++st == 3) st = 0;                                                     \
    }

// =============================================================================
// GEMM1: h = silu(x W1^T) * (x W3^T). B-rows 0..127 = gate, 128..255 = up.
// =============================================================================
__global__ __launch_bounds__(256, 1) void k_gemm1() {
    extern __shared__ __align__(16) char smraw[];
    const int mtile = blockIdx.x, ntile = blockIdx.y;  // mtile fast (A L2-reuse)
    if (mtile * 128 >= g_off[En]) return;
    int e = 0;
#pragma unroll
    for (int i = 0; i < En; i++) if (mtile * 128 >= g_off[i + 1]) e = i + 1;
    const int n0 = ntile * 128;
    const int tid = threadIdx.x;

    const uint32_t sb = smem_u32(smraw);
    const uint32_t sbA = sb, sbB = sb + BOFF_B;

    // loader slots: A 4x16B/thread/chunk, B 8x16B/thread/chunk
    const __half* pA[4]; uint32_t sAo[4];
    const __half* pB[8]; uint32_t sBo[8];
#pragma unroll
    for (int q = 0; q < 4; q++) {
        int u = tid + q * 256, r = u >> 3, sg = u & 7;
        pA[q] = g_xh + (size_t)(mtile * 128 + r) * Hn + sg * 8;
        sAo[q] = sbA + (r * 72 + sg * 8) * 2;
    }
#pragma unroll
    for (int q = 0; q < 8; q++) {
        int u = tid + q * 256, r = u >> 3, sg = u & 7;
        pB[q] = (r < 128)
            ? (g_w13h + ((size_t)e * 2 * In + n0 + r) * Hn + sg * 8)
            : (g_w13h + ((size_t)e * 2 * In + In + n0 + (r - 128)) * Hn + sg * 8);
        sBo[q] = sbB + (r * 72 + sg * 8) * 2;
    }

    const int w = tid >> 5, lane = tid & 31;
    const int mBase = (w & 1) * 64, nBase = (w >> 1) * 64;
    const int qr = lane >> 2, qc = lane & 3;
    const int loff = ldm_lane_off(lane);

    float acc[4][8][4];
#pragma unroll
    for (int a = 0; a < 4; a++)
#pragma unroll
        for (int b = 0; b < 8; b++)
#pragma unroll
            for (int c = 0; c < 4; c++) acc[a][b][c] = 0.0f;

    GEMM_MAINLOOP(Hn / 64)

    // ---- epilogue: gate warps stage to smem; up warps compute silu(g)*u ------
    float* sE = (float*)smraw;  // 128 x pitch-130 floats = 66,560 B (fits)
    if (nBase < 128) {
#pragma unroll
        for (int mi = 0; mi < 4; mi++)
#pragma unroll
            for (int ni = 0; ni < 8; ni++) {
                int r = mBase + mi * 16 + qr;
                int c = nBase + ni * 8 + qc * 2;
                sE[r * 130 + c] = acc[mi][ni][0];
                sE[r * 130 + c + 1] = acc[mi][ni][1];
                sE[(r + 8) * 130 + c] = acc[mi][ni][2];
                sE[(r + 8) * 130 + c + 1] = acc[mi][ni][3];
            }
    }
    __syncthreads();
    if (nBase >= 128) {
        const size_t rowBase = (size_t)mtile * 128;
#pragma unroll
        for (int mi = 0; mi < 4; mi++)
#pragma unroll
            for (int ni = 0; ni < 8; ni++) {
                int j = (nBase - 128) + ni * 8 + qc * 2;
#pragma unroll
                for (int half = 0; half < 2; half++) {
                    int r = mBase + mi * 16 + qr + half * 8;
                    float g0 = sE[r * 130 + j];
                    float g1 = sE[r * 130 + j + 1];
                    float u0 = acc[mi][ni][half * 2];
                    float u1 = acc[mi][ni][half * 2 + 1];
                    float h0 = g0 * (1.0f / (1.0f + __expf(-g0))) * u0;
                    float h1 = g1 * (1.0f / (1.0f + __expf(-g1))) * u1;
                    __half2 hv = __floats2half2_rn(h0, h1);
                    *(__half2*)&g_hbh[(rowBase + r) * In + (size_t)n0 + j] = hv;
                }
            }
    }
}

// =============================================================================
// GEMM2: po = wt * (h W2^T).  CTA tile M=128 x N=256 out cols, K = In.
// =============================================================================
__global__ __launch_bounds__(256, 1) void k_gemm2() {
    extern __shared__ __align__(16) char smraw[];
    const int ntile = blockIdx.x, mtile = blockIdx.y;  // ntile fast (w2 L2-resident)
    if (mtile * 128 >= g_off[En]) return;
    int e = 0;
#pragma unroll
    for (int i = 0; i < En; i++) if (mtile * 128 >= g_off[i + 1]) e = i + 1;
    const int n0 = ntile * 256;
    const int tid = threadIdx.x;

    const uint32_t sb = smem_u32(smraw);
    const uint32_t sbA = sb, sbB = sb + BOFF_B;

    const __half* pA[4]; uint32_t sAo[4];
    const __half* pB[8]; uint32_t sBo[8];
#pragma unroll
    for (int q = 0; q < 4; q++) {
        int u = tid + q * 256, r = u >> 3, sg = u & 7;
        pA[q] = g_hbh + (size_t)(mtile * 128 + r) * In + sg * 8;
        sAo[q] = sbA + (r * 72 + sg * 8) * 2;
    }
#pragma unroll
    for (int q = 0; q < 8; q++) {
        int u = tid + q * 256, r = u >> 3, sg = u & 7;
        pB[q] = g_w2h + ((size_t)e * Hn + n0 + r) * In + sg * 8;
        sBo[q] = sbB + (r * 72 + sg * 8) * 2;
    }

    const int w = tid >> 5, lane = tid & 31;
    const int mBase = (w & 1) * 64, nBase = (w >> 1) * 64;
    const int qr = lane >> 2, qc = lane & 3;
    const int loff = ldm_lane_off(lane);

    float acc[4][8][4];
#pragma unroll
    for (int a = 0; a < 4; a++)
#pragma unroll
        for (int b = 0; b < 8; b++)
#pragma unroll
            for (int c = 0; c < 4; c++) acc[a][b][c] = 0.0f;

    GEMM_MAINLOOP(In / 64)

    // ---- epilogue: scale by router weight, write per-pair fp16 output --------
    const size_t rowBase = (size_t)mtile * 128;
#pragma unroll
    for (int mi = 0; mi < 4; mi++) {
#pragma unroll
        for (int half = 0; half < 2; half++) {
            int r = mBase + mi * 16 + qr + half * 8;
            float wt = g_wt[rowBase + r];
#pragma unroll
            for (int ni = 0; ni < 8; ni++) {
                int c = nBase + ni * 8 + qc * 2;
                __half2 hv = __floats2half2_rn(wt * acc[mi][ni][half * 2],
                                               wt * acc[mi][ni][half * 2 + 1]);
                *(__half2*)&g_poh[(rowBase + r) * Hn + (size_t)n0 + c] = hv;
            }
        }
    }
}

// ------------------- combine: out[t] = po[slot0] + po[slot1] ------------------
__global__ void k_combine(float* __restrict__ out) {
    int t = blockIdx.x;
    int i = threadIdx.x;  // 256 threads x 4 halves
    int s0 = g_slots[2 * t], s1 = g_slots[2 * t + 1];
    uint2 pa = *(const uint2*)&g_poh[(size_t)s0 * Hn + i * 4];
    uint2 pb = *(const uint2*)&g_poh[(size_t)s1 * Hn + i * 4];
    float2 a0 = __half22float2(*(__half2*)&pa.x), a1 = __half22float2(*(__half2*)&pa.y);
    float2 b0 = __half22float2(*(__half2*)&pb.x), b1 = __half22float2(*(__half2*)&pb.y);
    float4 o;
    o.x = a0.x + b0.x; o.y = a0.y + b0.y; o.z = a1.x + b1.x; o.w = a1.y + b1.y;
    *(float4*)&out[(size_t)t * Hn + i * 4] = o;
}

// ------------------- launcher -------------------------------------------------
extern "C" void kernel_launch(void* const* d_in, const int* in_sizes, int n_in,
                              void* d_out, int out_size) {
    const float* x      = (const float*)d_in[0];
    const float* logits = (const float*)d_in[1];
    const float* w13    = (const float*)d_in[2];
    const float* w2     = (const float*)d_in[3];
    float* out = (float*)d_out;

    cudaFuncSetAttribute(k_gemm1, cudaFuncAttributeMaxDynamicSharedMemorySize, SMEM_BYTES);
    cudaFuncSetAttribute(k_gemm2, cudaFuncAttributeMaxDynamicSharedMemorySize, SMEM_BYTES);

    k_cvtw<<<2048, 256>>>(w13, w2);      // weights -> fp16, plus state init
    k_router<<<Tn / 256, 256>>>(logits);
    k_off<<<1, 32>>>();
    k_scatter<<<Tn / 256, 256>>>();
    k_gather<<<MAXP, 256>>>(x);
    k_gemm1<<<dim3(MAXP / 128, In / 128), 256, SMEM_BYTES>>>();  // (136, 22)
    k_gemm2<<<dim3(Hn / 256, MAXP / 128), 256, SMEM_BYTES>>>();  // (4, 136)
    k_combine<<<Tn, 256>>>(out);
}

// round 11
// speedup vs baseline: 2.9238x; 1.0083x over previous
#include <cuda_runtime.h>
#include <cuda_fp16.h>
#include <cstdint>

#define Tn 8192
#define Hn 1024
#define In 2816
#define En 8
#define MAXP 17408  // 16384 pairs + per-expert 128-alignment padding

// ------------------- device scratch (no allocations allowed) -----------------
__device__ int    g_cnt[En];
__device__ int    g_cur[En];
__device__ int    g_off[En + 1];
__device__ int    g_eid[Tn * 2];
__device__ float  g_ew[Tn * 2];
__device__ int    g_tok[MAXP];
__device__ float  g_wt[MAXP];
__device__ int    g_slots[Tn * 2];
__device__ __half g_xh[(size_t)MAXP * Hn];           // gathered x rows, fp16
__device__ __half g_hbh[(size_t)MAXP * In];          // silu(gate)*up, fp16
__device__ __half g_poh[(size_t)MAXP * Hn];          // per-pair weighted out, fp16
__device__ __half g_w13h[(size_t)En * 2 * In * Hn];  // fp16 w13 (92MB)
__device__ __half g_w2h[(size_t)En * Hn * In];       // fp16 w2  (46MB)

// ------------------- helpers -------------------------------------------------
__device__ __forceinline__ uint32_t smem_u32(const void* p) {
    uint32_t a;
    asm("{ .reg .u64 t; cvta.to.shared.u64 t, %1; cvt.u32.u64 %0, t; }" : "=r"(a) : "l"(p));
    return a;
}
__device__ __forceinline__ void cp16(uint32_t saddr, const void* gsrc) {
    asm volatile("cp.async.cg.shared.global [%0], [%1], 16;\n" :: "r"(saddr), "l"(gsrc));
}
// fp16 m16n8k16 mma, fp32 accumulate
__device__ __forceinline__ void mma16(float* c, const uint32_t* a, const uint32_t* b) {
    asm volatile(
        "mma.sync.aligned.m16n8k16.row.col.f32.f16.f16.f32 "
        "{%0,%1,%2,%3}, {%4,%5,%6,%7}, {%8,%9}, {%0,%1,%2,%3};\n"
        : "+f"(c[0]), "+f"(c[1]), "+f"(c[2]), "+f"(c[3])
        : "r"(a[0]), "r"(a[1]), "r"(a[2]), "r"(a[3]), "r"(b[0]), "r"(b[1]));
}
__device__ __forceinline__ void ldm4(uint32_t* r, uint32_t addr) {
    asm volatile("ldmatrix.sync.aligned.m8n8.x4.shared.b16 {%0,%1,%2,%3}, [%4];"
                 : "=r"(r[0]), "=r"(r[1]), "=r"(r[2]), "=r"(r[3]) : "r"(addr));
}
__device__ __forceinline__ uint32_t h2u(__half2 h) { return *(uint32_t*)&h; }

// smem layout: K-chunk = 128 halves (256 B/row), pitch 136 halves (272 B/row).
// Stage: A 128x272B = 34,816 B; B 256x272B = 69,632 B -> 104,448 B.
static constexpr int ROWP_B = 272;              // row pitch bytes
static constexpr int STG_B  = 104448;           // bytes per stage
static constexpr int BOFF_B = 34816;            // B offset within stage
static constexpr int SMEM_BYTES = STG_B * 2;    // 208,896 B (2 stages)

// ------------------- kernel: convert weights to fp16 (+ state init) ----------
__global__ void k_cvtw(const float* __restrict__ w13, const float* __restrict__ w2) {
    long gid = (long)blockIdx.x * blockDim.x + threadIdx.x;
    if (gid < En) { g_cnt[gid] = 0; g_cur[gid] = 0; }
    const long stride = (long)gridDim.x * blockDim.x;
    for (long s = gid; s < MAXP; s += stride) {
        g_tok[s] = -1;
        g_wt[s] = 0.0f;
    }
    const long N1 = (long)En * 2 * In * Hn / 4;
    const long N2 = (long)En * Hn * In / 4;
    for (long i = gid; i < N1 + N2; i += stride) {
        float4 v = (i < N1) ? ((const float4*)w13)[i] : ((const float4*)w2)[i - N1];
        uint2 pk;
        pk.x = h2u(__floats2half2_rn(v.x, v.y));
        pk.y = h2u(__floats2half2_rn(v.z, v.w));
        if (i < N1) ((uint2*)g_w13h)[i] = pk;
        else        ((uint2*)g_w2h)[i - N1] = pk;
    }
}

// ------------------- kernel: router ------------------------------------------
__global__ void k_router(const float* __restrict__ logits) {
    int t = blockIdx.x * blockDim.x + threadIdx.x;
    if (t >= Tn) return;
    float v[En];
#pragma unroll
    for (int e = 0; e < En; e++) v[e] = logits[t * En + e];
    int b0 = 0; float m0 = v[0];
#pragma unroll
    for (int e = 1; e < En; e++) if (v[e] > m0) { m0 = v[e]; b0 = e; }
    int b1 = -1; float m1 = -3.0e38f;
#pragma unroll
    for (int e = 0; e < En; e++) if (e != b0 && v[e] > m1) { m1 = v[e]; b1 = e; }
    float e1 = expf(m1 - m0);
    float inv = 1.0f / (1.0f + e1);
    g_eid[2 * t] = b0;     g_ew[2 * t] = inv;
    g_eid[2 * t + 1] = b1; g_ew[2 * t + 1] = e1 * inv;
    atomicAdd(&g_cnt[b0], 1);
    atomicAdd(&g_cnt[b1], 1);
}

// ------------------- kernel: 128-aligned offsets ------------------------------
__global__ void k_off() {
    if (threadIdx.x == 0 && blockIdx.x == 0) {
        int o = 0;
        g_off[0] = 0;
        for (int e = 0; e < En; e++) {
            o += (g_cnt[e] + 127) & ~127;
            g_off[e + 1] = o;
        }
    }
}

// ------------------- kernel: scatter ------------------------------------------
__global__ void k_scatter() {
    int t = blockIdx.x * blockDim.x + threadIdx.x;
    if (t >= Tn) return;
#pragma unroll
    for (int k = 0; k < 2; k++) {
        int e = g_eid[2 * t + k];
        int pos = atomicAdd(&g_cur[e], 1);
        int s = g_off[e] + pos;
        g_tok[s] = t;
        g_wt[s] = g_ew[2 * t + k];
        g_slots[2 * t + k] = s;
    }
}

// ------------------- kernel: gather x rows -> fp16 ----------------------------
__global__ void k_gather(const float* __restrict__ x) {
    int s = blockIdx.x;
    int tok = g_tok[s];
    uint2 pk = { 0u, 0u };
    if (tok >= 0) {
        float4 v = *(const float4*)&x[(size_t)tok * Hn + threadIdx.x * 4];
        pk.x = h2u(__floats2half2_rn(v.x, v.y));
        pk.y = h2u(__floats2half2_rn(v.z, v.w));
    }
    *(uint2*)&g_xh[(size_t)s * Hn + threadIdx.x * 4] = pk;
}

// =============================================================================
// GEMM mainloop: CTA tile M=128 x 256 B-rows, fp16 m16n8k16.
// K-chunk = 128 halves (256 B/row), pitch-136 smem rows, 2-stage cp.async
// pipeline (lookahead 1), ldmatrix fragment loads, 8 warps of 64x64.
// Loader per thread: r0 = tid>>4 (0..15), sg = tid&15 (16B segment);
// q steps advance 16 rows (A: q<8 covers 128 rows; B: q<16 covers 256 rows).
// =============================================================================

__device__ __forceinline__ int ldm_lane_off(int lane) {
    int lr = lane & 7, grp = lane >> 3;
    int rowoff = lr + (grp & 1) * 8;
    int coloff = (grp >> 1) * 8;
    return rowoff * ROWP_B + coloff * 2;
}

// B gmem address is kernel-specific: provide as macro B_ADDR(q) (chunk c in scope)
#define LOAD_CHUNK(c, st) do {                                                     \
    const uint32_t _sA = sA0 + (st) * STG_B;                                       \
    const uint32_t _sB = sB0 + (st) * STG_B;                                       \
    _Pragma("unroll")                                                              \
    for (int q = 0; q < 8; q++)                                                    \
        cp16(_sA + q * 16 * ROWP_B, pA0 + (size_t)q * 16 * strA + (c) * 128);      \
    _Pragma("unroll")                                                              \
    for (int q = 0; q < 16; q++)                                                   \
        cp16(_sB + q * 16 * ROWP_B, B_ADDR(q) + (c) * 128);                        \
    asm volatile("cp.async.commit_group;" ::: "memory");                           \
} while (0)

#define GEMM_MAINLOOP(NC)                                                          \
    LOAD_CHUNK(0, 0);                                                              \
    LOAD_CHUNK(1, 1);                                                              \
    for (int i = 0; i < (NC); i++) {                                               \
        const int st = i & 1;                                                      \
        asm volatile("cp.async.wait_group 1;" ::: "memory");                       \
        __syncthreads();                                                           \
        const uint32_t aS = sbA + st * STG_B;                                      \
        const uint32_t bS = sbB + st * STG_B;                                      \
        _Pragma("unroll")                                                          \
        for (int ks = 0; ks < 8; ks++) {                                           \
            const int k0b = ks * 32;                                               \
            uint32_t af[4][4], bf[8][2];                                           \
            _Pragma("unroll")                                                      \
            for (int mi = 0; mi < 4; mi++)                                         \
                ldm4(af[mi], aS + (mBase + mi * 16) * ROWP_B + k0b + loff);        \
            _Pragma("unroll")                                                      \
            for (int nj = 0; nj < 4; nj++) {                                       \
                uint32_t t4[4];                                                    \
                ldm4(t4, bS + (nBase + nj * 16) * ROWP_B + k0b + loff);            \
                bf[nj * 2][0] = t4[0]; bf[nj * 2 + 1][0] = t4[1];                  \
                bf[nj * 2][1] = t4[2]; bf[nj * 2 + 1][1] = t4[3];                  \
            }                                                                      \
            _Pragma("unroll")                                                      \
            for (int mi = 0; mi < 4; mi++)                                         \
                _Pragma("unroll")                                                  \
                for (int ni = 0; ni < 8; ni++) mma16(acc[mi][ni], af[mi], bf[ni]); \
        }                                                                          \
        __syncthreads();                                                           \
        if (i + 2 < (NC)) LOAD_CHUNK(i + 2, st);                                   \
        else asm volatile("cp.async.commit_group;" ::: "memory");                  \
    }

// =============================================================================
// GEMM1: h = silu(x W1^T) * (x W3^T). B-rows 0..127 = gate, 128..255 = up.
// =============================================================================
__global__ __launch_bounds__(256, 1) void k_gemm1() {
    extern __shared__ __align__(16) char smraw[];
    const int mtile = blockIdx.x, ntile = blockIdx.y;  // mtile fast (A L2-reuse)
    if (mtile * 128 >= g_off[En]) return;
    int e = 0;
#pragma unroll
    for (int i = 0; i < En; i++) if (mtile * 128 >= g_off[i + 1]) e = i + 1;
    const int n0 = ntile * 128;
    const int tid = threadIdx.x;

    const uint32_t sb = smem_u32(smraw);
    const uint32_t sbA = sb, sbB = sb + BOFF_B;

    // loader bases: r0 = tid>>4 (0..15), sg = tid&15
    const int r0 = tid >> 4, sg = tid & 15;
    const int strA = Hn;  // halves per A row
    const __half* pA0 = g_xh + (size_t)(mtile * 128 + r0) * Hn + sg * 8;
    const __half* pBg = g_w13h + ((size_t)e * 2 * In + n0 + r0) * Hn + sg * 8;
    const __half* pBu = g_w13h + ((size_t)e * 2 * In + In + n0 + r0) * Hn + sg * 8;
    const uint32_t sA0 = sbA + r0 * ROWP_B + sg * 16;
    const uint32_t sB0 = sbB + r0 * ROWP_B + sg * 16;
#define B_ADDR(q) ((q) < 8 ? (pBg + (size_t)(q) * 16 * Hn) : (pBu + (size_t)((q) - 8) * 16 * Hn))

    const int w = tid >> 5, lane = tid & 31;
    const int mBase = (w & 1) * 64, nBase = (w >> 1) * 64;
    const int qr = lane >> 2, qc = lane & 3;
    const int loff = ldm_lane_off(lane);

    float acc[4][8][4];
#pragma unroll
    for (int a = 0; a < 4; a++)
#pragma unroll
        for (int b = 0; b < 8; b++)
#pragma unroll
            for (int c = 0; c < 4; c++) acc[a][b][c] = 0.0f;

    GEMM_MAINLOOP(Hn / 128)  // 8 chunks
#undef B_ADDR

    // ---- epilogue: gate warps stage to smem; up warps compute silu(g)*u ------
    float* sE = (float*)smraw;  // 128 x pitch-130 floats = 66,560 B (fits)
    if (nBase < 128) {
#pragma unroll
        for (int mi = 0; mi < 4; mi++)
#pragma unroll
            for (int ni = 0; ni < 8; ni++) {
                int r = mBase + mi * 16 + qr;
                int c = nBase + ni * 8 + qc * 2;
                sE[r * 130 + c] = acc[mi][ni][0];
                sE[r * 130 + c + 1] = acc[mi][ni][1];
                sE[(r + 8) * 130 + c] = acc[mi][ni][2];
                sE[(r + 8) * 130 + c + 1] = acc[mi][ni][3];
            }
    }
    __syncthreads();
    if (nBase >= 128) {
        const size_t rowBase = (size_t)mtile * 128;
#pragma unroll
        for (int mi = 0; mi < 4; mi++)
#pragma unroll
            for (int ni = 0; ni < 8; ni++) {
                int j = (nBase - 128) + ni * 8 + qc * 2;
#pragma unroll
                for (int half = 0; half < 2; half++) {
                    int r = mBase + mi * 16 + qr + half * 8;
                    float g0 = sE[r * 130 + j];
                    float g1 = sE[r * 130 + j + 1];
                    float u0 = acc[mi][ni][half * 2];
                    float u1 = acc[mi][ni][half * 2 + 1];
                    float h0 = g0 * (1.0f / (1.0f + __expf(-g0))) * u0;
                    float h1 = g1 * (1.0f / (1.0f + __expf(-g1))) * u1;
                    __half2 hv = __floats2half2_rn(h0, h1);
                    *(__half2*)&g_hbh[(rowBase + r) * In + (size_t)n0 + j] = hv;
                }
            }
    }
}

// =============================================================================
// GEMM2: po = wt * (h W2^T).  CTA tile M=128 x N=256 out cols, K = In.
// =============================================================================
__global__ __launch_bounds__(256, 1) void k_gemm2() {
    extern __shared__ __align__(16) char smraw[];
    const int ntile = blockIdx.x, mtile = blockIdx.y;  // ntile fast (w2 L2-resident)
    if (mtile * 128 >= g_off[En]) return;
    int e = 0;
#pragma unroll
    for (int i = 0; i < En; i++) if (mtile * 128 >= g_off[i + 1]) e = i + 1;
    const int n0 = ntile * 256;
    const int tid = threadIdx.x;

    const uint32_t sb = smem_u32(smraw);
    const uint32_t sbA = sb, sbB = sb + BOFF_B;

    const int r0 = tid >> 4, sg = tid & 15;
    const int strA = In;
    const __half* pA0 = g_hbh + (size_t)(mtile * 128 + r0) * In + sg * 8;
    const __half* pB0 = g_w2h + ((size_t)e * Hn + n0 + r0) * In + sg * 8;
    const uint32_t sA0 = sbA + r0 * ROWP_B + sg * 16;
    const uint32_t sB0 = sbB + r0 * ROWP_B + sg * 16;
#define B_ADDR(q) (pB0 + (size_t)(q) * 16 * In)

    const int w = tid >> 5, lane = tid & 31;
    const int mBase = (w & 1) * 64, nBase = (w >> 1) * 64;
    const int qr = lane >> 2, qc = lane & 3;
    const int loff = ldm_lane_off(lane);

    float acc[4][8][4];
#pragma unroll
    for (int a = 0; a < 4; a++)
#pragma unroll
        for (int b = 0; b < 8; b++)
#pragma unroll
            for (int c = 0; c < 4; c++) acc[a][b][c] = 0.0f;

    GEMM_MAINLOOP(In / 128)  // 22 chunks
#undef B_ADDR

    // ---- epilogue: scale by router weight, write per-pair fp16 output --------
    const size_t rowBase = (size_t)mtile * 128;
#pragma unroll
    for (int mi = 0; mi < 4; mi++) {
#pragma unroll
        for (int half = 0; half < 2; half++) {
            int r = mBase + mi * 16 + qr + half * 8;
            float wt = g_wt[rowBase + r];
#pragma unroll
            for (int ni = 0; ni < 8; ni++) {
                int c = nBase + ni * 8 + qc * 2;
                __half2 hv = __floats2half2_rn(wt * acc[mi][ni][half * 2],
                                               wt * acc[mi][ni][half * 2 + 1]);
                *(__half2*)&g_poh[(rowBase + r) * Hn + (size_t)n0 + c] = hv;
            }
        }
    }
}

// ------------------- combine: out[t] = po[slot0] + po[slot1] ------------------
__global__ void k_combine(float* __restrict__ out) {
    int t = blockIdx.x;
    int i = threadIdx.x;  // 256 threads x 4 halves
    int s0 = g_slots[2 * t], s1 = g_slots[2 * t + 1];
    uint2 pa = *(const uint2*)&g_poh[(size_t)s0 * Hn + i * 4];
    uint2 pb = *(const uint2*)&g_poh[(size_t)s1 * Hn + i * 4];
    float2 a0 = __half22float2(*(__half2*)&pa.x), a1 = __half22float2(*(__half2*)&pa.y);
    float2 b0 = __half22float2(*(__half2*)&pb.x), b1 = __half22float2(*(__half2*)&pb.y);
    float4 o;
    o.x = a0.x + b0.x; o.y = a0.y + b0.y; o.z = a1.x + b1.x; o.w = a1.y + b1.y;
    *(float4*)&out[(size_t)t * Hn + i * 4] = o;
}

// ------------------- launcher -------------------------------------------------
extern "C" void kernel_launch(void* const* d_in, const int* in_sizes, int n_in,
                              void* d_out, int out_size) {
    const float* x      = (const float*)d_in[0];
    const float* logits = (const float*)d_in[1];
    const float* w13    = (const float*)d_in[2];
    const float* w2     = (const float*)d_in[3];
    float* out = (float*)d_out;

    cudaFuncSetAttribute(k_gemm1, cudaFuncAttributeMaxDynamicSharedMemorySize, SMEM_BYTES);
    cudaFuncSetAttribute(k_gemm2, cudaFuncAttributeMaxDynamicSharedMemorySize, SMEM_BYTES);

    k_cvtw<<<2048, 256>>>(w13, w2);      // weights -> fp16, plus state init
    k_router<<<Tn / 256, 256>>>(logits);
    k_off<<<1, 32>>>();
    k_scatter<<<Tn / 256, 256>>>();
    k_gather<<<MAXP, 256>>>(x);
    k_gemm1<<<dim3(MAXP / 128, In / 128), 256, SMEM_BYTES>>>();  // (136, 22)
    k_gemm2<<<dim3(Hn / 256, MAXP / 128), 256, SMEM_BYTES>>>();  // (4, 136)
    k_combine<<<Tn, 256>>>(out);
}